// round 1
// baseline (speedup 1.0000x reference)
#include <cuda_runtime.h>

// Problem constants
#define B_  4
#define S_  2048
#define D_  1024
#define H_  16
#define HD_ 64
#define M_  (B_*S_)   // 8192 rows for all projection GEMMs

// Scratch (allocation-free rule: __device__ globals)
__device__ float g_Q [(size_t)M_*D_];
__device__ float g_K [(size_t)M_*D_];
__device__ float g_V [(size_t)M_*D_];
__device__ float g_Hb[(size_t)M_*D_];

// ---------------------------------------------------------------------------
// GEMM: out[m,n] = sum_k X[m,k] * W[n,k] + bias[n]    (X @ W^T + b)
// M=8192, N=K=1024 hardcoded via D_. 64x64 tile, BK=16, 256 threads, 4x4/thread.
// ---------------------------------------------------------------------------
__global__ __launch_bounds__(256) void gemm_bias_kernel(
    const float* __restrict__ X, const float* __restrict__ W,
    const float* __restrict__ bias, float* __restrict__ out)
{
    __shared__ float Xs[16][64];
    __shared__ float Ws[16][64];
    const int tx = threadIdx.x, ty = threadIdx.y;
    const int tid = (ty << 4) | tx;
    const int m0 = blockIdx.y << 6, n0 = blockIdx.x << 6;
    const int lr = tid >> 2;          // 0..63: tile row this thread loads
    const int lk = (tid & 3) << 2;    // 0,4,8,12: k-offset (float4)

    float acc[4][4];
#pragma unroll
    for (int i = 0; i < 4; i++)
#pragma unroll
        for (int j = 0; j < 4; j++) acc[i][j] = 0.f;

    const float* Xp = X + (size_t)(m0 + lr) * D_ + lk;
    const float* Wp = W + (size_t)(n0 + lr) * D_ + lk;

    for (int k0 = 0; k0 < D_; k0 += 16) {
        float4 xv = *(const float4*)(Xp + k0);
        float4 wv = *(const float4*)(Wp + k0);
        Xs[lk + 0][lr] = xv.x; Xs[lk + 1][lr] = xv.y;
        Xs[lk + 2][lr] = xv.z; Xs[lk + 3][lr] = xv.w;
        Ws[lk + 0][lr] = wv.x; Ws[lk + 1][lr] = wv.y;
        Ws[lk + 2][lr] = wv.z; Ws[lk + 3][lr] = wv.w;
        __syncthreads();
#pragma unroll
        for (int kk = 0; kk < 16; kk++) {
            float4 a = *(const float4*)&Xs[kk][ty << 2];
            float4 b = *(const float4*)&Ws[kk][tx << 2];
            acc[0][0] += a.x*b.x; acc[0][1] += a.x*b.y; acc[0][2] += a.x*b.z; acc[0][3] += a.x*b.w;
            acc[1][0] += a.y*b.x; acc[1][1] += a.y*b.y; acc[1][2] += a.y*b.z; acc[1][3] += a.y*b.w;
            acc[2][0] += a.z*b.x; acc[2][1] += a.z*b.y; acc[2][2] += a.z*b.z; acc[2][3] += a.z*b.w;
            acc[3][0] += a.w*b.x; acc[3][1] += a.w*b.y; acc[3][2] += a.w*b.z; acc[3][3] += a.w*b.w;
        }
        __syncthreads();
    }

    float4 bv = *(const float4*)&bias[n0 + (tx << 2)];
#pragma unroll
    for (int i = 0; i < 4; i++) {
        float4 ov = make_float4(acc[i][0] + bv.x, acc[i][1] + bv.y,
                                acc[i][2] + bv.z, acc[i][3] + bv.w);
        *(float4*)&out[(size_t)(m0 + (ty << 2) + i) * D_ + n0 + (tx << 2)] = ov;
    }
}

// ---------------------------------------------------------------------------
// Flash attention, fp32, 64 query rows per block, Hd=64, online softmax.
// grid = (S/64, H, B), block = (16,16). Dynamic smem:
//   Qst[64][64] (d-major), Kts[64][64] (d-major), Vs[64][64], Ps[64][64], mk[64]
// ---------------------------------------------------------------------------
__global__ __launch_bounds__(256) void flash_kernel(const int* __restrict__ mask)
{
    extern __shared__ float smem[];
    float* Qst = smem;              // [d*64 + r]
    float* Kts = smem + 4096;       // [d*64 + j]
    float* Vs  = smem + 8192;       // [j*64 + c]
    float* Ps  = smem + 12288;      // [r*64 + j]
    int*   mk  = (int*)(smem + 16384);

    const int b  = blockIdx.z, h = blockIdx.y;
    const int q0 = blockIdx.x << 6;
    const int tx = threadIdx.x, ty = threadIdx.y;
    const int tid = (ty << 4) | tx;

    const int lr  = tid >> 2;         // 0..63
    const int ld0 = (tid & 3) << 4;   // 0,16,32,48

    // Load Q tile transposed: Qst[d][r] = Q[b, q0+r, h*64+d]
    {
        const float* Qg = g_Q + (size_t)(b * S_ + q0 + lr) * D_ + h * HD_ + ld0;
#pragma unroll
        for (int q = 0; q < 4; q++) {
            float4 v = *(const float4*)(Qg + (q << 2));
            int d = ld0 + (q << 2);
            Qst[(d + 0) * 64 + lr] = v.x; Qst[(d + 1) * 64 + lr] = v.y;
            Qst[(d + 2) * 64 + lr] = v.z; Qst[(d + 3) * 64 + lr] = v.w;
        }
    }

    float m_i[4], l_i[4], o[4][4];
#pragma unroll
    for (int i = 0; i < 4; i++) {
        m_i[i] = -1e30f; l_i[i] = 0.f;
#pragma unroll
        for (int j = 0; j < 4; j++) o[i][j] = 0.f;
    }

    const float* Kg0 = g_K + (size_t)(b * S_) * D_ + h * HD_;
    const float* Vg0 = g_V + (size_t)(b * S_) * D_ + h * HD_;
    const int*   mg  = mask + b * S_;

    for (int k0 = 0; k0 < S_; k0 += 64) {
        __syncthreads();   // previous PV finished reading Vs/Ps

        // K tile transposed: Kts[d][j] = K[b, k0+j, h*64+d]
        {
            const float* Kg = Kg0 + (size_t)(k0 + lr) * D_ + ld0;
#pragma unroll
            for (int q = 0; q < 4; q++) {
                float4 v = *(const float4*)(Kg + (q << 2));
                int d = ld0 + (q << 2);
                Kts[(d + 0) * 64 + lr] = v.x; Kts[(d + 1) * 64 + lr] = v.y;
                Kts[(d + 2) * 64 + lr] = v.z; Kts[(d + 3) * 64 + lr] = v.w;
            }
        }
        // V tile row-major
#pragma unroll
        for (int t = 0; t < 4; t++) {
            int idx = tid + (t << 8);          // float4 index 0..1023
            int r = idx >> 4, c = (idx & 15) << 2;
            *(float4*)&Vs[r * 64 + c] = *(const float4*)(Vg0 + (size_t)(k0 + r) * D_ + c);
        }
        if (tid < 64) mk[tid] = mg[k0 + tid];
        __syncthreads();

        // scores sc[i][j] = sum_d Q[ry][d]*K[jx][d]
        float sc[4][4];
#pragma unroll
        for (int i = 0; i < 4; i++)
#pragma unroll
            for (int j = 0; j < 4; j++) sc[i][j] = 0.f;

#pragma unroll 16
        for (int d = 0; d < 64; d++) {
            float4 a = *(const float4*)&Qst[d * 64 + (ty << 2)];
            float4 k = *(const float4*)&Kts[d * 64 + (tx << 2)];
            sc[0][0] += a.x*k.x; sc[0][1] += a.x*k.y; sc[0][2] += a.x*k.z; sc[0][3] += a.x*k.w;
            sc[1][0] += a.y*k.x; sc[1][1] += a.y*k.y; sc[1][2] += a.y*k.z; sc[1][3] += a.y*k.w;
            sc[2][0] += a.z*k.x; sc[2][1] += a.z*k.y; sc[2][2] += a.z*k.z; sc[2][3] += a.z*k.w;
            sc[3][0] += a.w*k.x; sc[3][1] += a.w*k.y; sc[3][2] += a.w*k.z; sc[3][3] += a.w*k.w;
        }

        // scale (1/sqrt(64)=0.125) and mask: masked -> exactly -1e10 (match ref)
        int mj0 = mk[(tx << 2) + 0], mj1 = mk[(tx << 2) + 1];
        int mj2 = mk[(tx << 2) + 2], mj3 = mk[(tx << 2) + 3];
#pragma unroll
        for (int i = 0; i < 4; i++) {
            sc[i][0] = (mj0 == 0) ? -1e10f : sc[i][0] * 0.125f;
            sc[i][1] = (mj1 == 0) ? -1e10f : sc[i][1] * 0.125f;
            sc[i][2] = (mj2 == 0) ? -1e10f : sc[i][2] * 0.125f;
            sc[i][3] = (mj3 == 0) ? -1e10f : sc[i][3] * 0.125f;
        }

        // online softmax update (row = 16 lanes: ty fixed, tx varies -> shfl over 16)
#pragma unroll
        for (int i = 0; i < 4; i++) {
            float tm = fmaxf(fmaxf(sc[i][0], sc[i][1]), fmaxf(sc[i][2], sc[i][3]));
#pragma unroll
            for (int off = 8; off; off >>= 1)
                tm = fmaxf(tm, __shfl_xor_sync(0xffffffffu, tm, off));
            float nm = fmaxf(m_i[i], tm);
            float al = __expf(m_i[i] - nm);
            float rs = 0.f;
#pragma unroll
            for (int j = 0; j < 4; j++) {
                float p = __expf(sc[i][j] - nm);
                sc[i][j] = p; rs += p;
            }
#pragma unroll
            for (int off = 8; off; off >>= 1)
                rs += __shfl_xor_sync(0xffffffffu, rs, off);
            l_i[i] = l_i[i] * al + rs;
            m_i[i] = nm;
            o[i][0] *= al; o[i][1] *= al; o[i][2] *= al; o[i][3] *= al;
            *(float4*)&Ps[((ty << 2) + i) * 64 + (tx << 2)] =
                make_float4(sc[i][0], sc[i][1], sc[i][2], sc[i][3]);
        }
        __syncthreads();

        // O += P @ V
#pragma unroll 8
        for (int j = 0; j < 64; j++) {
            float4 vv = *(const float4*)&Vs[j * 64 + (tx << 2)];
            float p0 = Ps[((ty << 2) + 0) * 64 + j];
            float p1 = Ps[((ty << 2) + 1) * 64 + j];
            float p2 = Ps[((ty << 2) + 2) * 64 + j];
            float p3 = Ps[((ty << 2) + 3) * 64 + j];
            o[0][0] += p0*vv.x; o[0][1] += p0*vv.y; o[0][2] += p0*vv.z; o[0][3] += p0*vv.w;
            o[1][0] += p1*vv.x; o[1][1] += p1*vv.y; o[1][2] += p1*vv.z; o[1][3] += p1*vv.w;
            o[2][0] += p2*vv.x; o[2][1] += p2*vv.y; o[2][2] += p2*vv.z; o[2][3] += p2*vv.w;
            o[3][0] += p3*vv.x; o[3][1] += p3*vv.y; o[3][2] += p3*vv.z; o[3][3] += p3*vv.w;
        }
    }

    // normalize & write h (merged heads layout: [B,S,D] with head at h*64)
#pragma unroll
    for (int i = 0; i < 4; i++) {
        float inv = 1.f / l_i[i];
        float4 ov = make_float4(o[i][0]*inv, o[i][1]*inv, o[i][2]*inv, o[i][3]*inv);
        *(float4*)&g_Hb[(size_t)(b * S_ + q0 + (ty << 2) + i) * D_ + h * HD_ + (tx << 2)] = ov;
    }
}

// ---------------------------------------------------------------------------
extern "C" void kernel_launch(void* const* d_in, const int* in_sizes, int n_in,
                              void* d_out, int out_size)
{
    const float* query = (const float*)d_in[0];
    const float* key   = (const float*)d_in[1];
    const float* value = (const float*)d_in[2];
    const int*   mask  = (const int*)d_in[3];
    const float* Wq = (const float*)d_in[4];
    const float* bq = (const float*)d_in[5];
    const float* Wk = (const float*)d_in[6];
    const float* bk = (const float*)d_in[7];
    const float* Wv = (const float*)d_in[8];
    const float* bv = (const float*)d_in[9];
    const float* Wo = (const float*)d_in[10];
    const float* bo = (const float*)d_in[11];
    float* out = (float*)d_out;

    float *qb, *kb, *vb, *hb;
    cudaGetSymbolAddress((void**)&qb, g_Q);
    cudaGetSymbolAddress((void**)&kb, g_K);
    cudaGetSymbolAddress((void**)&vb, g_V);
    cudaGetSymbolAddress((void**)&hb, g_Hb);

    static int smem_set = 0;
    const int FLASH_SMEM = (4 * 4096 + 64) * 4;   // 65792 B
    if (!smem_set) {
        cudaFuncSetAttribute(flash_kernel,
                             cudaFuncAttributeMaxDynamicSharedMemorySize, FLASH_SMEM);
        smem_set = 1;
    }

    dim3 blk(16, 16);
    dim3 ggrid(D_ / 64, M_ / 64);                 // (16, 128)
    gemm_bias_kernel<<<ggrid, blk>>>(query, Wq, bq, qb);
    gemm_bias_kernel<<<ggrid, blk>>>(key,   Wk, bk, kb);
    gemm_bias_kernel<<<ggrid, blk>>>(value, Wv, bv, vb);
    flash_kernel<<<dim3(S_ / 64, H_, B_), blk, FLASH_SMEM>>>(mask);
    gemm_bias_kernel<<<ggrid, blk>>>(hb, Wo, bo, out);
}

// round 5
// speedup vs baseline: 1.5646x; 1.5646x over previous
#include <cuda_runtime.h>
#include <cuda_bf16.h>
#include <cstdint>

// Problem constants
#define B_  4
#define S_  2048
#define D_  1024
#define H_  16
#define HD_ 64
#define M_  (B_*S_)   // 8192

// ---------------- scratch (__device__ globals; no allocs allowed) ----------
__device__ float g_Q [(size_t)M_*D_];
__device__ float g_K [(size_t)M_*D_];
__device__ float g_V [(size_t)M_*D_];
__device__ float g_Hb[(size_t)M_*D_];

__device__ __nv_bfloat16 g_xq_h[(size_t)M_*D_], g_xq_l[(size_t)M_*D_];
__device__ __nv_bfloat16 g_xk_h[(size_t)M_*D_], g_xk_l[(size_t)M_*D_];
__device__ __nv_bfloat16 g_xv_h[(size_t)M_*D_], g_xv_l[(size_t)M_*D_];
__device__ __nv_bfloat16 g_h_h [(size_t)M_*D_], g_h_l [(size_t)M_*D_];
__device__ __nv_bfloat16 g_wq_h[(size_t)D_*D_], g_wq_l[(size_t)D_*D_];
__device__ __nv_bfloat16 g_wk_h[(size_t)D_*D_], g_wk_l[(size_t)D_*D_];
__device__ __nv_bfloat16 g_wv_h[(size_t)D_*D_], g_wv_l[(size_t)D_*D_];
__device__ __nv_bfloat16 g_wo_h[(size_t)D_*D_], g_wo_l[(size_t)D_*D_];

// single dynamic-smem symbol shared by all kernels (char; cast per kernel)
extern __shared__ char dynsmem[];

// ---------------- PTX helpers (baseline features only) ----------------------
__device__ __forceinline__ uint32_t smem_u32(const void* p) {
    uint32_t a;
    asm("{ .reg .u64 t; cvta.to.shared.u64 t, %1; cvt.u32.u64 %0, t; }" : "=r"(a) : "l"(p));
    return a;
}
__device__ __forceinline__ void cp16(uint32_t dst, const void* src) {
    asm volatile("cp.async.cg.shared.global [%0], [%1], 16;" :: "r"(dst), "l"(src) : "memory");
}
__device__ __forceinline__ void cp_commit() {
    asm volatile("cp.async.commit_group;" ::: "memory");
}
__device__ __forceinline__ void ldsm4(uint32_t* r, uint32_t addr) {
    asm volatile("ldmatrix.sync.aligned.m8n8.x4.shared.b16 {%0,%1,%2,%3}, [%4];"
                 : "=r"(r[0]), "=r"(r[1]), "=r"(r[2]), "=r"(r[3]) : "r"(addr));
}
__device__ __forceinline__ void mma_bf16(float* d, const uint32_t* a, const uint32_t* b) {
    asm volatile(
        "mma.sync.aligned.m16n8k16.row.col.f32.bf16.bf16.f32 "
        "{%0,%1,%2,%3}, {%4,%5,%6,%7}, {%8,%9}, {%0,%1,%2,%3};"
        : "+f"(d[0]), "+f"(d[1]), "+f"(d[2]), "+f"(d[3])
        : "r"(a[0]), "r"(a[1]), "r"(a[2]), "r"(a[3]), "r"(b[0]), "r"(b[1]));
}
// packed f32x2 helpers
__device__ __forceinline__ unsigned long long pk2(float x, float y) {
    unsigned long long r;
    asm("mov.b64 %0, {%1, %2};" : "=l"(r) : "f"(x), "f"(y));
    return r;
}
__device__ __forceinline__ void fma2(unsigned long long& acc, unsigned long long a,
                                     unsigned long long b) {
    asm("fma.rn.f32x2 %0, %1, %2, %0;" : "+l"(acc) : "l"(a), "l"(b));
}
__device__ __forceinline__ unsigned long long mul2(unsigned long long a, unsigned long long b) {
    unsigned long long r;
    asm("mul.rn.f32x2 %0, %1, %2;" : "=l"(r) : "l"(a), "l"(b));
    return r;
}
__device__ __forceinline__ float2 upk(unsigned long long v) {
    float2 f;
    asm("mov.b64 {%0, %1}, %2;" : "=f"(f.x), "=f"(f.y) : "l"(v));
    return f;
}

// ---------------- fp32 -> bf16 hi/lo split ----------------------------------
__global__ __launch_bounds__(256) void cvt_split_kernel(
    const float* __restrict__ x, __nv_bfloat16* __restrict__ hi,
    __nv_bfloat16* __restrict__ lo, int n4)
{
    int i = blockIdx.x * blockDim.x + threadIdx.x;
    if (i >= n4) return;
    float4 v = ((const float4*)x)[i];
    __nv_bfloat16 h0 = __float2bfloat16(v.x), h1 = __float2bfloat16(v.y);
    __nv_bfloat16 h2 = __float2bfloat16(v.z), h3 = __float2bfloat16(v.w);
    __nv_bfloat16 l0 = __float2bfloat16(v.x - __bfloat162float(h0));
    __nv_bfloat16 l1 = __float2bfloat16(v.y - __bfloat162float(h1));
    __nv_bfloat16 l2 = __float2bfloat16(v.z - __bfloat162float(h2));
    __nv_bfloat16 l3 = __float2bfloat16(v.w - __bfloat162float(h3));
    __nv_bfloat162 hh0; hh0.x = h0; hh0.y = h1;
    __nv_bfloat162 hh1; hh1.x = h2; hh1.y = h3;
    __nv_bfloat162 ll0; ll0.x = l0; ll0.y = l1;
    __nv_bfloat162 ll1; ll1.x = l2; ll1.y = l3;
    ((__nv_bfloat162*)hi)[i * 2 + 0] = hh0;
    ((__nv_bfloat162*)hi)[i * 2 + 1] = hh1;
    ((__nv_bfloat162*)lo)[i * 2 + 0] = ll0;
    ((__nv_bfloat162*)lo)[i * 2 + 1] = ll1;
}

// ---------------- mma.sync bf16 GEMM: out = A @ B^T + bias ------------------
// CTA tile 128x128, BK=32, 8 warps (2 x 4), warp tile 64x32.
// 3-pass hi/lo split: Ah*Bh + Ah*Bl + Al*Bh, fp32 accumulate.
#define BM 128
#define BN 128
#define GBK 32
#define ROWB 80                 // padded row stride in bytes (40 bf16) - conflict-free
#define TILEB (128 * ROWB)      // 10240 bytes per (hi or lo) tile
#define BUFB  (4 * TILEB)       // Ah, Al, Bh, Bl
#define GEMM_SMEM (2 * BUFB)    // 81920

__device__ __forceinline__ void g2s_chunk(
    uint32_t sbuf,
    const __nv_bfloat16* Ah, const __nv_bfloat16* Al,
    const __nv_bfloat16* Bh, const __nv_bfloat16* Bl, int tid)
{
#pragma unroll
    for (int r = 0; r < 2; r++) {
        int c = tid + (r << 8);
        int row = c >> 2, c16 = c & 3;
        uint32_t soff = (uint32_t)row * ROWB + (uint32_t)c16 * 16;
        size_t goff = (size_t)row * D_ + c16 * 8;
        cp16(sbuf + 0 * TILEB + soff, Ah + goff);
        cp16(sbuf + 1 * TILEB + soff, Al + goff);
        cp16(sbuf + 2 * TILEB + soff, Bh + goff);
        cp16(sbuf + 3 * TILEB + soff, Bl + goff);
    }
}

__global__ __launch_bounds__(256) void gemm_mma_kernel(
    const __nv_bfloat16* __restrict__ Ahi, const __nv_bfloat16* __restrict__ Alo,
    const __nv_bfloat16* __restrict__ Bhi, const __nv_bfloat16* __restrict__ Blo,
    const float* __restrict__ bias, float* __restrict__ out)
{
    const uint32_t sb = smem_u32(dynsmem);
    const int tid = threadIdx.x, wid = tid >> 5, lane = tid & 31;
    const int wm = wid >> 2, wn = wid & 3;          // warp grid 2 x 4
    const int n0 = blockIdx.x * BN, m0 = blockIdx.y * BM;

    const __nv_bfloat16* Ah = Ahi + (size_t)m0 * D_;
    const __nv_bfloat16* Al = Alo + (size_t)m0 * D_;
    const __nv_bfloat16* Bh = Bhi + (size_t)n0 * D_;
    const __nv_bfloat16* Bl = Blo + (size_t)n0 * D_;

    float acc[4][4][4];
#pragma unroll
    for (int i = 0; i < 4; i++)
#pragma unroll
        for (int j = 0; j < 4; j++)
#pragma unroll
            for (int k = 0; k < 4; k++) acc[i][j][k] = 0.f;

    // prologue: chunks 0 and 1
    g2s_chunk(sb,        Ah,      Al,      Bh,      Bl,      tid); cp_commit();
    g2s_chunk(sb + BUFB, Ah + GBK, Al + GBK, Bh + GBK, Bl + GBK, tid); cp_commit();

    // ldmatrix lane addressing (non-trans for BOTH A and B: both stored
    // [rows][k] row-major, which is exactly the row.col operand layout)
    const int lr = lane & 7, lq = lane >> 3;
    // A: r0=(m0-7,k0-7) r1=(m8-15,k0-7) r2=(m0-7,k8-15) r3=(m8-15,k8-15)
    const uint32_t a_base_off =
        (uint32_t)(wm * 64 + (lq & 1) * 8 + lr) * ROWB + (uint32_t)((lq >> 1) * 8) * 2;
    // B: r0=(n0-7,k0-7) r1=(n0-7,k8-15) r2=(n8-15,k0-7) r3=(n8-15,k8-15)
    const uint32_t b_base_off =
        (uint32_t)(wn * 32 + (lq >> 1) * 8 + lr) * ROWB + (uint32_t)((lq & 1) * 8) * 2;

    const int NCHUNK = D_ / GBK;   // 32
#pragma unroll 1
    for (int c = 0; c < NCHUNK; c++) {
        if (c >= NCHUNK - 2) asm volatile("cp.async.wait_group 0;" ::: "memory");
        else                 asm volatile("cp.async.wait_group 1;" ::: "memory");
        __syncthreads();

        const uint32_t buf = sb + (uint32_t)(c & 1) * BUFB;
        const uint32_t sAh = buf + 0 * TILEB, sAl = buf + 1 * TILEB;
        const uint32_t sBh = buf + 2 * TILEB, sBl = buf + 3 * TILEB;

#pragma unroll
        for (int ks = 0; ks < 2; ks++) {
            const uint32_t ko = (uint32_t)(ks * 16) * 2;   // byte offset of k-step
            uint32_t ahr[4][4], alr[4][4], bhr[2][4], blr[2][4];
#pragma unroll
            for (int mt = 0; mt < 4; mt++) {
                ldsm4(ahr[mt], sAh + a_base_off + ko + (uint32_t)mt * (16 * ROWB));
                ldsm4(alr[mt], sAl + a_base_off + ko + (uint32_t)mt * (16 * ROWB));
            }
#pragma unroll
            for (int np = 0; np < 2; np++) {
                ldsm4(bhr[np], sBh + b_base_off + ko + (uint32_t)np * (16 * ROWB));
                ldsm4(blr[np], sBl + b_base_off + ko + (uint32_t)np * (16 * ROWB));
            }
#pragma unroll
            for (int mt = 0; mt < 4; mt++)
#pragma unroll
                for (int nt = 0; nt < 4; nt++) {
                    const uint32_t* bh2 = &bhr[nt >> 1][(nt & 1) * 2];
                    const uint32_t* bl2 = &blr[nt >> 1][(nt & 1) * 2];
                    mma_bf16(acc[mt][nt], ahr[mt], bh2);
                    mma_bf16(acc[mt][nt], ahr[mt], bl2);
                    mma_bf16(acc[mt][nt], alr[mt], bh2);
                }
        }
        __syncthreads();

        if (c + 2 < NCHUNK) {
            const int kc = (c + 2) * GBK;
            g2s_chunk(sb + (uint32_t)(c & 1) * BUFB,
                      Ah + kc, Al + kc, Bh + kc, Bl + kc, tid);
            cp_commit();
        }
    }

    // epilogue
    const int g = lane >> 2, tq = lane & 3;
#pragma unroll
    for (int mt = 0; mt < 4; mt++) {
#pragma unroll
        for (int nt = 0; nt < 4; nt++) {
            int row = m0 + wm * 64 + mt * 16 + g;
            int col = n0 + wn * 32 + nt * 8 + tq * 2;
            float2 bv = *(const float2*)&bias[col];
            float2 o0 = make_float2(acc[mt][nt][0] + bv.x, acc[mt][nt][1] + bv.y);
            float2 o1 = make_float2(acc[mt][nt][2] + bv.x, acc[mt][nt][3] + bv.y);
            *(float2*)&out[(size_t)row * D_ + col]       = o0;
            *(float2*)&out[(size_t)(row + 8) * D_ + col] = o1;
        }
    }
}

// ---------------- flash attention (fp32, f32x2 packed FMA) ------------------
__global__ __launch_bounds__(256) void flash_kernel(const int* __restrict__ mask)
{
    float* smem = (float*)dynsmem;
    float* Qst = smem;              // [d*64 + r]
    float* Kts = smem + 4096;       // [d*64 + j]
    float* Vs  = smem + 8192;       // [j*64 + c]
    float* Ps  = smem + 12288;      // [r*64 + j]
    int*   mk  = (int*)(smem + 16384);

    const int b  = blockIdx.z, h = blockIdx.y;
    const int q0 = blockIdx.x << 6;
    const int tx = threadIdx.x, ty = threadIdx.y;
    const int tid = (ty << 4) | tx;

    const int lr  = tid >> 2;
    const int ld0 = (tid & 3) << 4;

    {
        const float* Qg = g_Q + (size_t)(b * S_ + q0 + lr) * D_ + h * HD_ + ld0;
#pragma unroll
        for (int q = 0; q < 4; q++) {
            float4 v = *(const float4*)(Qg + (q << 2));
            int d = ld0 + (q << 2);
            Qst[(d + 0) * 64 + lr] = v.x; Qst[(d + 1) * 64 + lr] = v.y;
            Qst[(d + 2) * 64 + lr] = v.z; Qst[(d + 3) * 64 + lr] = v.w;
        }
    }

    float m_i[4], l_i[4];
    unsigned long long o2[4][2];
#pragma unroll
    for (int i = 0; i < 4; i++) {
        m_i[i] = -1e30f; l_i[i] = 0.f;
        o2[i][0] = 0ull; o2[i][1] = 0ull;
    }

    const float* Kg0 = g_K + (size_t)(b * S_) * D_ + h * HD_;
    const float* Vg0 = g_V + (size_t)(b * S_) * D_ + h * HD_;
    const int*   mg  = mask + b * S_;

    for (int k0 = 0; k0 < S_; k0 += 64) {
        __syncthreads();

        {
            const float* Kg = Kg0 + (size_t)(k0 + lr) * D_ + ld0;
#pragma unroll
            for (int q = 0; q < 4; q++) {
                float4 v = *(const float4*)(Kg + (q << 2));
                int d = ld0 + (q << 2);
                Kts[(d + 0) * 64 + lr] = v.x; Kts[(d + 1) * 64 + lr] = v.y;
                Kts[(d + 2) * 64 + lr] = v.z; Kts[(d + 3) * 64 + lr] = v.w;
            }
        }
#pragma unroll
        for (int t = 0; t < 4; t++) {
            int idx = tid + (t << 8);
            int r = idx >> 4, c = (idx & 15) << 2;
            *(float4*)&Vs[r * 64 + c] = *(const float4*)(Vg0 + (size_t)(k0 + r) * D_ + c);
        }
        if (tid < 64) mk[tid] = mg[k0 + tid];
        __syncthreads();

        // QK^T with packed FFMA2
        unsigned long long acc2[4][2];
#pragma unroll
        for (int i = 0; i < 4; i++) { acc2[i][0] = 0ull; acc2[i][1] = 0ull; }

#pragma unroll 16
        for (int d = 0; d < 64; d++) {
            float4 a = *(const float4*)&Qst[d * 64 + (ty << 2)];
            const unsigned long long* kp =
                (const unsigned long long*)&Kts[d * 64 + (tx << 2)];
            unsigned long long k01 = kp[0], k23 = kp[1];
            unsigned long long a0 = pk2(a.x, a.x), a1 = pk2(a.y, a.y);
            unsigned long long a2 = pk2(a.z, a.z), a3 = pk2(a.w, a.w);
            fma2(acc2[0][0], a0, k01); fma2(acc2[0][1], a0, k23);
            fma2(acc2[1][0], a1, k01); fma2(acc2[1][1], a1, k23);
            fma2(acc2[2][0], a2, k01); fma2(acc2[2][1], a2, k23);
            fma2(acc2[3][0], a3, k01); fma2(acc2[3][1], a3, k23);
        }

        float sc[4][4];
#pragma unroll
        for (int i = 0; i < 4; i++) {
            float2 u0 = upk(acc2[i][0]), u1 = upk(acc2[i][1]);
            sc[i][0] = u0.x; sc[i][1] = u0.y; sc[i][2] = u1.x; sc[i][3] = u1.y;
        }

        int mj0 = mk[(tx << 2) + 0], mj1 = mk[(tx << 2) + 1];
        int mj2 = mk[(tx << 2) + 2], mj3 = mk[(tx << 2) + 3];
#pragma unroll
        for (int i = 0; i < 4; i++) {
            sc[i][0] = (mj0 == 0) ? -1e10f : sc[i][0] * 0.125f;
            sc[i][1] = (mj1 == 0) ? -1e10f : sc[i][1] * 0.125f;
            sc[i][2] = (mj2 == 0) ? -1e10f : sc[i][2] * 0.125f;
            sc[i][3] = (mj3 == 0) ? -1e10f : sc[i][3] * 0.125f;
        }

#pragma unroll
        for (int i = 0; i < 4; i++) {
            float tm = fmaxf(fmaxf(sc[i][0], sc[i][1]), fmaxf(sc[i][2], sc[i][3]));
#pragma unroll
            for (int off = 8; off; off >>= 1)
                tm = fmaxf(tm, __shfl_xor_sync(0xffffffffu, tm, off));
            float nm = fmaxf(m_i[i], tm);
            float al = __expf(m_i[i] - nm);
            float rs = 0.f;
#pragma unroll
            for (int j = 0; j < 4; j++) {
                float p = __expf(sc[i][j] - nm);
                sc[i][j] = p; rs += p;
            }
#pragma unroll
            for (int off = 8; off; off >>= 1)
                rs += __shfl_xor_sync(0xffffffffu, rs, off);
            l_i[i] = l_i[i] * al + rs;
            m_i[i] = nm;
            unsigned long long pal = pk2(al, al);
            o2[i][0] = mul2(o2[i][0], pal);
            o2[i][1] = mul2(o2[i][1], pal);
            *(float4*)&Ps[((ty << 2) + i) * 64 + (tx << 2)] =
                make_float4(sc[i][0], sc[i][1], sc[i][2], sc[i][3]);
        }
        __syncthreads();

        // O += P @ V with packed FFMA2
#pragma unroll 8
        for (int j = 0; j < 64; j++) {
            const unsigned long long* vp =
                (const unsigned long long*)&Vs[j * 64 + (tx << 2)];
            unsigned long long v01 = vp[0], v23 = vp[1];
            float p0 = Ps[((ty << 2) + 0) * 64 + j];
            float p1 = Ps[((ty << 2) + 1) * 64 + j];
            float p2 = Ps[((ty << 2) + 2) * 64 + j];
            float p3 = Ps[((ty << 2) + 3) * 64 + j];
            unsigned long long q0 = pk2(p0, p0), q1 = pk2(p1, p1);
            unsigned long long q2 = pk2(p2, p2), q3 = pk2(p3, p3);
            fma2(o2[0][0], q0, v01); fma2(o2[0][1], q0, v23);
            fma2(o2[1][0], q1, v01); fma2(o2[1][1], q1, v23);
            fma2(o2[2][0], q2, v01); fma2(o2[2][1], q2, v23);
            fma2(o2[3][0], q3, v01); fma2(o2[3][1], q3, v23);
        }
    }

#pragma unroll
    for (int i = 0; i < 4; i++) {
        float inv = 1.f / l_i[i];
        float2 u0 = upk(o2[i][0]), u1 = upk(o2[i][1]);
        float4 ov = make_float4(u0.x * inv, u0.y * inv, u1.x * inv, u1.y * inv);
        *(float4*)&g_Hb[(size_t)(b * S_ + q0 + (ty << 2) + i) * D_ + h * HD_ + (tx << 2)] = ov;
    }
}

// ---------------------------------------------------------------------------
extern "C" void kernel_launch(void* const* d_in, const int* in_sizes, int n_in,
                              void* d_out, int out_size)
{
    const float* query = (const float*)d_in[0];
    const float* key   = (const float*)d_in[1];
    const float* value = (const float*)d_in[2];
    const int*   mask  = (const int*)d_in[3];
    const float* Wq = (const float*)d_in[4];
    const float* bq = (const float*)d_in[5];
    const float* Wk = (const float*)d_in[6];
    const float* bk = (const float*)d_in[7];
    const float* Wv = (const float*)d_in[8];
    const float* bv = (const float*)d_in[9];
    const float* Wo = (const float*)d_in[10];
    const float* bo = (const float*)d_in[11];
    float* out = (float*)d_out;

    float *qb, *kb, *vb, *hb;
    cudaGetSymbolAddress((void**)&qb, g_Q);
    cudaGetSymbolAddress((void**)&kb, g_K);
    cudaGetSymbolAddress((void**)&vb, g_V);
    cudaGetSymbolAddress((void**)&hb, g_Hb);

    __nv_bfloat16 *xqh,*xql,*xkh,*xkl,*xvh,*xvl,*hh,*hl;
    __nv_bfloat16 *wqh,*wql,*wkh,*wkl,*wvh,*wvl,*woh,*wol;
    cudaGetSymbolAddress((void**)&xqh, g_xq_h); cudaGetSymbolAddress((void**)&xql, g_xq_l);
    cudaGetSymbolAddress((void**)&xkh, g_xk_h); cudaGetSymbolAddress((void**)&xkl, g_xk_l);
    cudaGetSymbolAddress((void**)&xvh, g_xv_h); cudaGetSymbolAddress((void**)&xvl, g_xv_l);
    cudaGetSymbolAddress((void**)&hh,  g_h_h);  cudaGetSymbolAddress((void**)&hl,  g_h_l);
    cudaGetSymbolAddress((void**)&wqh, g_wq_h); cudaGetSymbolAddress((void**)&wql, g_wq_l);
    cudaGetSymbolAddress((void**)&wkh, g_wk_h); cudaGetSymbolAddress((void**)&wkl, g_wk_l);
    cudaGetSymbolAddress((void**)&wvh, g_wv_h); cudaGetSymbolAddress((void**)&wvl, g_wv_l);
    cudaGetSymbolAddress((void**)&woh, g_wo_h); cudaGetSymbolAddress((void**)&wol, g_wo_l);

    static int attr_set = 0;
    const int FLASH_SMEM = (4 * 4096 + 64) * 4;   // 65792 B
    if (!attr_set) {
        cudaFuncSetAttribute(flash_kernel,
                             cudaFuncAttributeMaxDynamicSharedMemorySize, FLASH_SMEM);
        cudaFuncSetAttribute(gemm_mma_kernel,
                             cudaFuncAttributeMaxDynamicSharedMemorySize, GEMM_SMEM);
        attr_set = 1;
    }

    const int NX4 = M_ * D_ / 4;
    const int NW4 = D_ * D_ / 4;
    cvt_split_kernel<<<(NX4 + 255) / 256, 256>>>(query, xqh, xql, NX4);
    cvt_split_kernel<<<(NX4 + 255) / 256, 256>>>(key,   xkh, xkl, NX4);
    cvt_split_kernel<<<(NX4 + 255) / 256, 256>>>(value, xvh, xvl, NX4);
    cvt_split_kernel<<<(NW4 + 255) / 256, 256>>>(Wq, wqh, wql, NW4);
    cvt_split_kernel<<<(NW4 + 255) / 256, 256>>>(Wk, wkh, wkl, NW4);
    cvt_split_kernel<<<(NW4 + 255) / 256, 256>>>(Wv, wvh, wvl, NW4);
    cvt_split_kernel<<<(NW4 + 255) / 256, 256>>>(Wo, woh, wol, NW4);

    dim3 ggrid(D_ / BN, M_ / BM);   // (8, 64)
    gemm_mma_kernel<<<ggrid, 256, GEMM_SMEM>>>(xqh, xql, wqh, wql, bq, qb);
    gemm_mma_kernel<<<ggrid, 256, GEMM_SMEM>>>(xkh, xkl, wkh, wkl, bk, kb);
    gemm_mma_kernel<<<ggrid, 256, GEMM_SMEM>>>(xvh, xvl, wvh, wvl, bv, vb);

    flash_kernel<<<dim3(S_ / 64, H_, B_), dim3(16, 16), FLASH_SMEM>>>(mask);

    cvt_split_kernel<<<(NX4 + 255) / 256, 256>>>(hb, hh, hl, NX4);
    gemm_mma_kernel<<<ggrid, 256, GEMM_SMEM>>>(hh, hl, woh, wol, bo, out);
}

// round 6
// speedup vs baseline: 2.5638x; 1.6386x over previous
#include <cuda_runtime.h>
#include <cuda_bf16.h>
#include <cstdint>

// Problem constants
#define B_  4
#define S_  2048
#define D_  1024
#define H_  16
#define HD_ 64
#define M_  (B_*S_)   // 8192

// ---------------- scratch (__device__ globals; no allocs allowed) ----------
// input activations / weights, split hi/lo
__device__ __nv_bfloat16 g_xq_h[(size_t)M_*D_], g_xq_l[(size_t)M_*D_];
__device__ __nv_bfloat16 g_xk_h[(size_t)M_*D_], g_xk_l[(size_t)M_*D_];
__device__ __nv_bfloat16 g_xv_h[(size_t)M_*D_], g_xv_l[(size_t)M_*D_];
__device__ __nv_bfloat16 g_wq_h[(size_t)D_*D_], g_wq_l[(size_t)D_*D_];
__device__ __nv_bfloat16 g_wk_h[(size_t)D_*D_], g_wk_l[(size_t)D_*D_];
__device__ __nv_bfloat16 g_wv_h[(size_t)D_*D_], g_wv_l[(size_t)D_*D_];
__device__ __nv_bfloat16 g_wo_h[(size_t)D_*D_], g_wo_l[(size_t)D_*D_];
// projected Q,K,V split hi/lo in head-compact layout [b,h,s,d]
__device__ __nv_bfloat16 g_qh[(size_t)M_*D_], g_ql[(size_t)M_*D_];
__device__ __nv_bfloat16 g_kh[(size_t)M_*D_], g_kl[(size_t)M_*D_];
__device__ __nv_bfloat16 g_vh[(size_t)M_*D_], g_vl[(size_t)M_*D_];
// V transposed [b,h,d,s]
__device__ __nv_bfloat16 g_vth[(size_t)M_*D_], g_vtl[(size_t)M_*D_];
// attention output split hi/lo in [m][1024] layout (A of final GEMM)
__device__ __nv_bfloat16 g_hh[(size_t)M_*D_], g_hl[(size_t)M_*D_];

// single dynamic-smem symbol shared by all kernels
extern __shared__ char dynsmem[];

// ---------------- PTX helpers (family-portable features only) ---------------
__device__ __forceinline__ uint32_t smem_u32(const void* p) {
    uint32_t a;
    asm("{ .reg .u64 t; cvta.to.shared.u64 t, %1; cvt.u32.u64 %0, t; }" : "=r"(a) : "l"(p));
    return a;
}
__device__ __forceinline__ void cp16(uint32_t dst, const void* src) {
    asm volatile("cp.async.cg.shared.global [%0], [%1], 16;" :: "r"(dst), "l"(src) : "memory");
}
__device__ __forceinline__ void cp_commit() {
    asm volatile("cp.async.commit_group;" ::: "memory");
}
__device__ __forceinline__ void ldsm4(uint32_t* r, uint32_t addr) {
    asm volatile("ldmatrix.sync.aligned.m8n8.x4.shared.b16 {%0,%1,%2,%3}, [%4];"
                 : "=r"(r[0]), "=r"(r[1]), "=r"(r[2]), "=r"(r[3]) : "r"(addr));
}
__device__ __forceinline__ void mma_bf16(float* d, const uint32_t* a, const uint32_t* b) {
    asm volatile(
        "mma.sync.aligned.m16n8k16.row.col.f32.bf16.bf16.f32 "
        "{%0,%1,%2,%3}, {%4,%5,%6,%7}, {%8,%9}, {%0,%1,%2,%3};"
        : "+f"(d[0]), "+f"(d[1]), "+f"(d[2]), "+f"(d[3])
        : "r"(a[0]), "r"(a[1]), "r"(a[2]), "r"(a[3]), "r"(b[0]), "r"(b[1]));
}
// pack two fp32 -> bf16x2 (lo in low half), plus residual pair
__device__ __forceinline__ uint32_t cvt2bf(float lo, float hi) {
    uint32_t r;
    asm("cvt.rn.bf16x2.f32 %0, %1, %2;" : "=r"(r) : "f"(hi), "f"(lo));
    return r;
}
__device__ __forceinline__ void split2(float x0, float x1, uint32_t& hp, uint32_t& lp) {
    hp = cvt2bf(x0, x1);
    float h0 = __uint_as_float(hp << 16);
    float h1 = __uint_as_float(hp & 0xffff0000u);
    lp = cvt2bf(x0 - h0, x1 - h1);
}

// ---------------- fp32 -> bf16 hi/lo split ----------------------------------
__global__ __launch_bounds__(256) void cvt_split_kernel(
    const float* __restrict__ x, __nv_bfloat16* __restrict__ hi,
    __nv_bfloat16* __restrict__ lo, int n4)
{
    int i = blockIdx.x * blockDim.x + threadIdx.x;
    if (i >= n4) return;
    float4 v = ((const float4*)x)[i];
    uint32_t h0, l0, h1, l1;
    split2(v.x, v.y, h0, l0);
    split2(v.z, v.w, h1, l1);
    ((uint32_t*)hi)[i * 2 + 0] = h0;
    ((uint32_t*)hi)[i * 2 + 1] = h1;
    ((uint32_t*)lo)[i * 2 + 0] = l0;
    ((uint32_t*)lo)[i * 2 + 1] = l1;
}

// ---------------- mma.sync bf16 GEMM: out = A @ B^T + bias ------------------
// CTA tile 128x128, BK=32, 8 warps (2 x 4), warp tile 64x32.
// 3-pass hi/lo split. EPI=0: fp32 out [m][D]. EPI=1: split bf16 out,
// head-compact [b,h,s,d].
#define BM 128
#define BN 128
#define GBK 32
#define ROWB 80
#define TILEB (128 * ROWB)
#define BUFB  (4 * TILEB)
#define GEMM_SMEM (2 * BUFB)    // 81920

__device__ __forceinline__ void g2s_chunk(
    uint32_t sbuf,
    const __nv_bfloat16* Ah, const __nv_bfloat16* Al,
    const __nv_bfloat16* Bh, const __nv_bfloat16* Bl, int tid)
{
#pragma unroll
    for (int r = 0; r < 2; r++) {
        int c = tid + (r << 8);
        int row = c >> 2, c16 = c & 3;
        uint32_t soff = (uint32_t)row * ROWB + (uint32_t)c16 * 16;
        size_t goff = (size_t)row * D_ + c16 * 8;
        cp16(sbuf + 0 * TILEB + soff, Ah + goff);
        cp16(sbuf + 1 * TILEB + soff, Al + goff);
        cp16(sbuf + 2 * TILEB + soff, Bh + goff);
        cp16(sbuf + 3 * TILEB + soff, Bl + goff);
    }
}

template <int EPI>
__global__ __launch_bounds__(256) void gemm_mma_kernel(
    const __nv_bfloat16* __restrict__ Ahi, const __nv_bfloat16* __restrict__ Alo,
    const __nv_bfloat16* __restrict__ Bhi, const __nv_bfloat16* __restrict__ Blo,
    const float* __restrict__ bias, float* __restrict__ out,
    __nv_bfloat16* __restrict__ outh, __nv_bfloat16* __restrict__ outl)
{
    const uint32_t sb = smem_u32(dynsmem);
    const int tid = threadIdx.x, wid = tid >> 5, lane = tid & 31;
    const int wm = wid >> 2, wn = wid & 3;
    const int n0 = blockIdx.x * BN, m0 = blockIdx.y * BM;

    const __nv_bfloat16* Ah = Ahi + (size_t)m0 * D_;
    const __nv_bfloat16* Al = Alo + (size_t)m0 * D_;
    const __nv_bfloat16* Bh = Bhi + (size_t)n0 * D_;
    const __nv_bfloat16* Bl = Blo + (size_t)n0 * D_;

    float acc[4][4][4];
#pragma unroll
    for (int i = 0; i < 4; i++)
#pragma unroll
        for (int j = 0; j < 4; j++)
#pragma unroll
            for (int k = 0; k < 4; k++) acc[i][j][k] = 0.f;

    g2s_chunk(sb,        Ah,       Al,       Bh,       Bl,       tid); cp_commit();
    g2s_chunk(sb + BUFB, Ah + GBK, Al + GBK, Bh + GBK, Bl + GBK, tid); cp_commit();

    const int lr = lane & 7, lq = lane >> 3;
    const uint32_t a_base_off =
        (uint32_t)(wm * 64 + (lq & 1) * 8 + lr) * ROWB + (uint32_t)((lq >> 1) * 8) * 2;
    const uint32_t b_base_off =
        (uint32_t)(wn * 32 + (lq >> 1) * 8 + lr) * ROWB + (uint32_t)((lq & 1) * 8) * 2;

    const int NCHUNK = D_ / GBK;
#pragma unroll 1
    for (int c = 0; c < NCHUNK; c++) {
        if (c >= NCHUNK - 2) asm volatile("cp.async.wait_group 0;" ::: "memory");
        else                 asm volatile("cp.async.wait_group 1;" ::: "memory");
        __syncthreads();

        const uint32_t buf = sb + (uint32_t)(c & 1) * BUFB;
        const uint32_t sAh = buf + 0 * TILEB, sAl = buf + 1 * TILEB;
        const uint32_t sBh = buf + 2 * TILEB, sBl = buf + 3 * TILEB;

#pragma unroll
        for (int ks = 0; ks < 2; ks++) {
            const uint32_t ko = (uint32_t)(ks * 16) * 2;
            uint32_t ahr[4][4], alr[4][4], bhr[2][4], blr[2][4];
#pragma unroll
            for (int mt = 0; mt < 4; mt++) {
                ldsm4(ahr[mt], sAh + a_base_off + ko + (uint32_t)mt * (16 * ROWB));
                ldsm4(alr[mt], sAl + a_base_off + ko + (uint32_t)mt * (16 * ROWB));
            }
#pragma unroll
            for (int np = 0; np < 2; np++) {
                ldsm4(bhr[np], sBh + b_base_off + ko + (uint32_t)np * (16 * ROWB));
                ldsm4(blr[np], sBl + b_base_off + ko + (uint32_t)np * (16 * ROWB));
            }
#pragma unroll
            for (int mt = 0; mt < 4; mt++)
#pragma unroll
                for (int nt = 0; nt < 4; nt++) {
                    const uint32_t* bh2 = &bhr[nt >> 1][(nt & 1) * 2];
                    const uint32_t* bl2 = &blr[nt >> 1][(nt & 1) * 2];
                    mma_bf16(acc[mt][nt], ahr[mt], bh2);
                    mma_bf16(acc[mt][nt], ahr[mt], bl2);
                    mma_bf16(acc[mt][nt], alr[mt], bh2);
                }
        }
        __syncthreads();

        if (c + 2 < NCHUNK) {
            const int kc = (c + 2) * GBK;
            g2s_chunk(sb + (uint32_t)(c & 1) * BUFB,
                      Ah + kc, Al + kc, Bh + kc, Bl + kc, tid);
            cp_commit();
        }
    }

    const int g = lane >> 2, tq = lane & 3;
#pragma unroll
    for (int mt = 0; mt < 4; mt++) {
#pragma unroll
        for (int nt = 0; nt < 4; nt++) {
            int row = m0 + wm * 64 + mt * 16 + g;
            int col = n0 + wn * 32 + nt * 8 + tq * 2;
            float2 bv = *(const float2*)&bias[col];
            float v0 = acc[mt][nt][0] + bv.x, v1 = acc[mt][nt][1] + bv.y;
            float v2 = acc[mt][nt][2] + bv.x, v3 = acc[mt][nt][3] + bv.y;
            if (EPI == 0) {
                *(float2*)&out[(size_t)row * D_ + col]       = make_float2(v0, v1);
                *(float2*)&out[(size_t)(row + 8) * D_ + col] = make_float2(v2, v3);
            } else {
                int bb = row >> 11, s = row & 2047, hh = col >> 6, d = col & 63;
                size_t i0 = ((size_t)(bb * H_ + hh) * S_ + s) * HD_ + d;
                size_t i1 = i0 + 8 * HD_;   // row+8 -> s+8 (same b: s<2040 within tile ok)
                uint32_t hp, lp;
                split2(v0, v1, hp, lp);
                *(uint32_t*)&outh[i0] = hp; *(uint32_t*)&outl[i0] = lp;
                split2(v2, v3, hp, lp);
                *(uint32_t*)&outh[i1] = hp; *(uint32_t*)&outl[i1] = lp;
            }
        }
    }
}

// ---------------- V transpose: [b,h,s,d] -> [b,h,d,s] (hi and lo) ----------
__global__ __launch_bounds__(256) void vtrans_kernel()
{
    __shared__ __align__(16) unsigned short ts[64 * 66];
    const int b = blockIdx.z, h = blockIdx.y, st = blockIdx.x;
    const int bh = b * H_ + h;
    const int s0 = st * 64;
    const int tid = threadIdx.x;

#pragma unroll 1
    for (int p = 0; p < 2; p++) {
        if (p) __syncthreads();
        const __nv_bfloat16* inp = (p ? g_vl : g_vh) + ((size_t)bh * S_ + s0) * HD_;
        const uint32_t* src = (const uint32_t*)inp;
#pragma unroll
        for (int i = 0; i < 8; i++) {
            int flat = tid + i * 256;
            int r = flat >> 5, c2 = flat & 31;
            *(uint32_t*)&ts[r * 66 + c2 * 2] = src[r * 32 + c2];
        }
        __syncthreads();
        __nv_bfloat16* outp = (p ? g_vtl : g_vth) + (size_t)bh * HD_ * S_ + s0;
        uint32_t* dst = (uint32_t*)outp;
#pragma unroll
        for (int i = 0; i < 8; i++) {
            int flat = tid + i * 256;
            int d = flat >> 5, sp = flat & 31;
            uint32_t v = (uint32_t)ts[(2 * sp) * 66 + d] |
                         ((uint32_t)ts[(2 * sp + 1) * 66 + d] << 16);
            dst[(size_t)d * (S_ / 2) + sp] = v;
        }
    }
}

// ---------------- tensor-core flash attention --------------------------------
// grid (16 qtiles, 16 h, 4 b), 256 threads (8 warps x 16 q-rows).
// smem: Qh[128][72bf16]@144B, Ql; double-buffered {Kh,Kl,Vth,Vtl} 64x144B; mask.
#define FQ_H 0u
#define FQ_L 18432u
#define FKV  36864u          // + buf*36864; inside: Kh,Kl,Vh,Vl each 9216
#define FMK  110592u         // + buf*256
#define FLASH_SMEM 111104

__global__ __launch_bounds__(256) void flash_tc_kernel(const int* __restrict__ mask)
{
    char* sm = dynsmem;
    const uint32_t sb = smem_u32(sm);
    const int tid = threadIdx.x, w = tid >> 5, lane = tid & 31;
    const int lr = lane & 7, lq = lane >> 3, g = lane >> 2, q = lane & 3;
    const int b = blockIdx.z, h = blockIdx.y;
    const int bh = b * H_ + h;
    const int q0 = blockIdx.x * 128;

    const __nv_bfloat16* Qhp = g_qh + ((size_t)bh * S_ + q0) * HD_;
    const __nv_bfloat16* Qlp = g_ql + ((size_t)bh * S_ + q0) * HD_;
    const __nv_bfloat16* Khp = g_kh + (size_t)bh * S_ * HD_;
    const __nv_bfloat16* Klp = g_kl + (size_t)bh * S_ * HD_;
    const __nv_bfloat16* Vhp = g_vth + (size_t)bh * HD_ * S_;
    const __nv_bfloat16* Vlp = g_vtl + (size_t)bh * HD_ * S_;
    const int* mg = mask + b * S_;

    // Q tile -> smem
    {
        int r = tid >> 1, half = tid & 1;
        const __nv_bfloat16* src = (half ? Qlp : Qhp) + (size_t)r * HD_;
        uint32_t dst = sb + (half ? FQ_L : FQ_H) + (uint32_t)r * 144u;
#pragma unroll
        for (int j = 0; j < 8; j++) cp16(dst + j * 16, src + j * 8);
    }
    cp_commit();

    auto load_tile = [&](int kt, int buf) {
        int k0 = kt * 64;
        int r = tid >> 2, which = tid & 3;
        uint32_t dst = sb + FKV + (uint32_t)buf * 36864u +
                       (uint32_t)which * 9216u + (uint32_t)r * 144u;
        const __nv_bfloat16* src;
        if (which == 0)      src = Khp + (size_t)(k0 + r) * HD_;
        else if (which == 1) src = Klp + (size_t)(k0 + r) * HD_;
        else if (which == 2) src = Vhp + (size_t)r * S_ + k0;
        else                 src = Vlp + (size_t)r * S_ + k0;
#pragma unroll
        for (int j = 0; j < 8; j++) cp16(dst + j * 16, src + j * 8);
        if (tid < 16) cp16(sb + FMK + (uint32_t)buf * 256u + tid * 16, mg + k0 + tid * 4);
        cp_commit();
    };
    load_tile(0, 0);
    load_tile(1, 1);

    asm volatile("cp.async.wait_group 2;" ::: "memory");
    __syncthreads();

    // Q fragments (register resident, 4 k-steps x hi/lo)
    uint32_t qfh[4][4], qfl[4][4];
    {
        uint32_t aoff = (uint32_t)(w * 16 + (lq & 1) * 8 + lr) * 144u +
                        (uint32_t)((lq >> 1) * 8) * 2u;
#pragma unroll
        for (int ks = 0; ks < 4; ks++) {
            ldsm4(qfh[ks], sb + FQ_H + aoff + ks * 32);
            ldsm4(qfl[ks], sb + FQ_L + aoff + ks * 32);
        }
    }

    float o[8][4];
#pragma unroll
    for (int i = 0; i < 8; i++) { o[i][0] = o[i][1] = o[i][2] = o[i][3] = 0.f; }
    float m0r = -1e30f, m1r = -1e30f, l0 = 0.f, l1 = 0.f;
    const uint32_t boff = (uint32_t)((lq >> 1) * 8 + lr) * 144u +
                          (uint32_t)((lq & 1) * 8) * 2u;

#pragma unroll 1
    for (int kt = 0; kt < 32; kt++) {
        if (kt >= 30) asm volatile("cp.async.wait_group 0;" ::: "memory");
        else          asm volatile("cp.async.wait_group 1;" ::: "memory");
        __syncthreads();

        const uint32_t kb = sb + FKV + (uint32_t)(kt & 1) * 36864u;
        const int* mkb = (const int*)(sm + FMK + (kt & 1) * 256);

        // ---- scores: S = Q @ K^T (3-pass split) ----
        float sc[8][4];
#pragma unroll
        for (int i = 0; i < 8; i++) { sc[i][0] = sc[i][1] = sc[i][2] = sc[i][3] = 0.f; }

#pragma unroll
        for (int ks = 0; ks < 4; ks++) {
            uint32_t kfh[4][4], kfl[4][4];
#pragma unroll
            for (int np = 0; np < 4; np++) {
                ldsm4(kfh[np], kb + boff + (uint32_t)np * 2304u + ks * 32);
                ldsm4(kfl[np], kb + 9216u + boff + (uint32_t)np * 2304u + ks * 32);
            }
#pragma unroll
            for (int nt = 0; nt < 8; nt++) {
                const uint32_t* bh2 = &kfh[nt >> 1][(nt & 1) * 2];
                const uint32_t* bl2 = &kfl[nt >> 1][(nt & 1) * 2];
                mma_bf16(sc[nt], qfh[ks], bh2);
                mma_bf16(sc[nt], qfh[ks], bl2);
                mma_bf16(sc[nt], qfl[ks], bh2);
            }
        }

        // ---- scale + mask ----
#pragma unroll
        for (int nt = 0; nt < 8; nt++) {
            int c0 = nt * 8 + q * 2;
            int mk0 = mkb[c0], mk1 = mkb[c0 + 1];
            sc[nt][0] = mk0 ? sc[nt][0] * 0.125f : -1e10f;
            sc[nt][1] = mk1 ? sc[nt][1] * 0.125f : -1e10f;
            sc[nt][2] = mk0 ? sc[nt][2] * 0.125f : -1e10f;
            sc[nt][3] = mk1 ? sc[nt][3] * 0.125f : -1e10f;
        }

        // ---- online softmax (rows g and g+8; quad = lanes xor {1,2}) ----
        float tm0 = -1e30f, tm1 = -1e30f;
#pragma unroll
        for (int nt = 0; nt < 8; nt++) {
            tm0 = fmaxf(tm0, fmaxf(sc[nt][0], sc[nt][1]));
            tm1 = fmaxf(tm1, fmaxf(sc[nt][2], sc[nt][3]));
        }
        tm0 = fmaxf(tm0, __shfl_xor_sync(0xffffffffu, tm0, 1));
        tm0 = fmaxf(tm0, __shfl_xor_sync(0xffffffffu, tm0, 2));
        tm1 = fmaxf(tm1, __shfl_xor_sync(0xffffffffu, tm1, 1));
        tm1 = fmaxf(tm1, __shfl_xor_sync(0xffffffffu, tm1, 2));
        float nm0 = fmaxf(m0r, tm0), nm1 = fmaxf(m1r, tm1);
        float al0 = __expf(m0r - nm0), al1 = __expf(m1r - nm1);
        m0r = nm0; m1r = nm1;
        float rs0 = 0.f, rs1 = 0.f;
#pragma unroll
        for (int nt = 0; nt < 8; nt++) {
            sc[nt][0] = __expf(sc[nt][0] - nm0);
            sc[nt][1] = __expf(sc[nt][1] - nm0);
            sc[nt][2] = __expf(sc[nt][2] - nm1);
            sc[nt][3] = __expf(sc[nt][3] - nm1);
            rs0 += sc[nt][0] + sc[nt][1];
            rs1 += sc[nt][2] + sc[nt][3];
        }
        rs0 += __shfl_xor_sync(0xffffffffu, rs0, 1);
        rs0 += __shfl_xor_sync(0xffffffffu, rs0, 2);
        rs1 += __shfl_xor_sync(0xffffffffu, rs1, 1);
        rs1 += __shfl_xor_sync(0xffffffffu, rs1, 2);
        l0 = l0 * al0 + rs0;
        l1 = l1 * al1 + rs1;
#pragma unroll
        for (int nt = 0; nt < 8; nt++) {
            o[nt][0] *= al0; o[nt][1] *= al0; o[nt][2] *= al1; o[nt][3] *= al1;
        }

        // ---- O += P @ V (P in registers, 3-pass split) ----
#pragma unroll
        for (int ks = 0; ks < 4; ks++) {
            const int t0 = 2 * ks, t1 = t0 + 1;
            uint32_t ah[4], apl[4];
            split2(sc[t0][0], sc[t0][1], ah[0], apl[0]);
            split2(sc[t0][2], sc[t0][3], ah[1], apl[1]);
            split2(sc[t1][0], sc[t1][1], ah[2], apl[2]);
            split2(sc[t1][2], sc[t1][3], ah[3], apl[3]);
            uint32_t vfh[4][4], vfl[4][4];
#pragma unroll
            for (int np = 0; np < 4; np++) {
                ldsm4(vfh[np], kb + 18432u + boff + (uint32_t)np * 2304u + ks * 32);
                ldsm4(vfl[np], kb + 27648u + boff + (uint32_t)np * 2304u + ks * 32);
            }
#pragma unroll
            for (int nt = 0; nt < 8; nt++) {
                const uint32_t* bh2 = &vfh[nt >> 1][(nt & 1) * 2];
                const uint32_t* bl2 = &vfl[nt >> 1][(nt & 1) * 2];
                mma_bf16(o[nt], ah, bh2);
                mma_bf16(o[nt], apl, bh2);
                mma_bf16(o[nt], ah, bl2);
            }
        }
        __syncthreads();
        if (kt + 2 < 32) load_tile(kt + 2, kt & 1);
    }

    // ---- normalize, split, store to [m][1024] hi/lo ----
    float inv0 = 1.f / l0, inv1 = 1.f / l1;
    size_t row0 = (size_t)(b * S_ + q0 + w * 16 + g);
    int colb = h * HD_;
#pragma unroll
    for (int nt = 0; nt < 8; nt++) {
        int col = colb + nt * 8 + q * 2;
        uint32_t hp, lp;
        split2(o[nt][0] * inv0, o[nt][1] * inv0, hp, lp);
        *(uint32_t*)&g_hh[row0 * D_ + col] = hp;
        *(uint32_t*)&g_hl[row0 * D_ + col] = lp;
        split2(o[nt][2] * inv1, o[nt][3] * inv1, hp, lp);
        *(uint32_t*)&g_hh[(row0 + 8) * D_ + col] = hp;
        *(uint32_t*)&g_hl[(row0 + 8) * D_ + col] = lp;
    }
}

// ---------------------------------------------------------------------------
extern "C" void kernel_launch(void* const* d_in, const int* in_sizes, int n_in,
                              void* d_out, int out_size)
{
    const float* query = (const float*)d_in[0];
    const float* key   = (const float*)d_in[1];
    const float* value = (const float*)d_in[2];
    const int*   mask  = (const int*)d_in[3];
    const float* Wq = (const float*)d_in[4];
    const float* bq = (const float*)d_in[5];
    const float* Wk = (const float*)d_in[6];
    const float* bk = (const float*)d_in[7];
    const float* Wv = (const float*)d_in[8];
    const float* bv = (const float*)d_in[9];
    const float* Wo = (const float*)d_in[10];
    const float* bo = (const float*)d_in[11];
    float* out = (float*)d_out;

    __nv_bfloat16 *xqh,*xql,*xkh,*xkl,*xvh,*xvl;
    __nv_bfloat16 *wqh,*wql,*wkh,*wkl,*wvh,*wvl,*woh,*wol;
    __nv_bfloat16 *qh,*ql,*kh,*kl,*vh,*vl,*hh,*hl;
    cudaGetSymbolAddress((void**)&xqh, g_xq_h); cudaGetSymbolAddress((void**)&xql, g_xq_l);
    cudaGetSymbolAddress((void**)&xkh, g_xk_h); cudaGetSymbolAddress((void**)&xkl, g_xk_l);
    cudaGetSymbolAddress((void**)&xvh, g_xv_h); cudaGetSymbolAddress((void**)&xvl, g_xv_l);
    cudaGetSymbolAddress((void**)&wqh, g_wq_h); cudaGetSymbolAddress((void**)&wql, g_wq_l);
    cudaGetSymbolAddress((void**)&wkh, g_wk_h); cudaGetSymbolAddress((void**)&wkl, g_wk_l);
    cudaGetSymbolAddress((void**)&wvh, g_wv_h); cudaGetSymbolAddress((void**)&wvl, g_wv_l);
    cudaGetSymbolAddress((void**)&woh, g_wo_h); cudaGetSymbolAddress((void**)&wol, g_wo_l);
    cudaGetSymbolAddress((void**)&qh, g_qh);    cudaGetSymbolAddress((void**)&ql, g_ql);
    cudaGetSymbolAddress((void**)&kh, g_kh);    cudaGetSymbolAddress((void**)&kl, g_kl);
    cudaGetSymbolAddress((void**)&vh, g_vh);    cudaGetSymbolAddress((void**)&vl, g_vl);
    cudaGetSymbolAddress((void**)&hh, g_hh);    cudaGetSymbolAddress((void**)&hl, g_hl);

    static int attr_set = 0;
    if (!attr_set) {
        cudaFuncSetAttribute(gemm_mma_kernel<0>,
                             cudaFuncAttributeMaxDynamicSharedMemorySize, GEMM_SMEM);
        cudaFuncSetAttribute(gemm_mma_kernel<1>,
                             cudaFuncAttributeMaxDynamicSharedMemorySize, GEMM_SMEM);
        cudaFuncSetAttribute(flash_tc_kernel,
                             cudaFuncAttributeMaxDynamicSharedMemorySize, FLASH_SMEM);
        attr_set = 1;
    }

    const int NX4 = M_ * D_ / 4;
    const int NW4 = D_ * D_ / 4;
    cvt_split_kernel<<<(NX4 + 255) / 256, 256>>>(query, xqh, xql, NX4);
    cvt_split_kernel<<<(NX4 + 255) / 256, 256>>>(key,   xkh, xkl, NX4);
    cvt_split_kernel<<<(NX4 + 255) / 256, 256>>>(value, xvh, xvl, NX4);
    cvt_split_kernel<<<(NW4 + 255) / 256, 256>>>(Wq, wqh, wql, NW4);
    cvt_split_kernel<<<(NW4 + 255) / 256, 256>>>(Wk, wkh, wkl, NW4);
    cvt_split_kernel<<<(NW4 + 255) / 256, 256>>>(Wv, wvh, wvl, NW4);
    cvt_split_kernel<<<(NW4 + 255) / 256, 256>>>(Wo, woh, wol, NW4);

    dim3 ggrid(D_ / BN, M_ / BM);   // (8, 64)
    gemm_mma_kernel<1><<<ggrid, 256, GEMM_SMEM>>>(xqh, xql, wqh, wql, bq, nullptr, qh, ql);
    gemm_mma_kernel<1><<<ggrid, 256, GEMM_SMEM>>>(xkh, xkl, wkh, wkl, bk, nullptr, kh, kl);
    gemm_mma_kernel<1><<<ggrid, 256, GEMM_SMEM>>>(xvh, xvl, wvh, wvl, bv, nullptr, vh, vl);

    vtrans_kernel<<<dim3(S_ / 64, H_, B_), 256>>>();

    flash_tc_kernel<<<dim3(S_ / 128, H_, B_), 256, FLASH_SMEM>>>(mask);

    gemm_mma_kernel<0><<<ggrid, 256, GEMM_SMEM>>>(hh, hl, woh, wol, bo, out, nullptr, nullptr);
}